// round 2
// baseline (speedup 1.0000x reference)
#include <cuda_runtime.h>
#include <math.h>

// Problem constants
#define B_   8
#define C_   256
#define CI_  128
#define H_   64
#define W_   64
#define N_   4096      // H*W
#define M_   1024      // (H/2)*(W/2)
#define PAD  132

// Scratch (device globals: allocation-free per harness rules)
__device__ float g_Q  [(size_t)B_ * N_ * CI_];   // [b][n][ci]
__device__ float g_Kv [(size_t)B_ * M_ * CI_];   // [b][m][ci]
__device__ float g_Vv [(size_t)B_ * M_ * CI_];   // [b][m][ci]
__device__ float g_S  [(size_t)B_ * N_ * M_];    // [b][n][m]
__device__ float g_Y  [(size_t)B_ * N_ * CI_];   // [b][n][ci]
__device__ float g_Wy [(size_t)B_ * C_ * N_];    // [b][o][n]
__device__ float g_sum  [C_];
__device__ float g_sumsq[C_];

// ---------------------------------------------------------------------------
// Shared 128x128-tile fp32 GEMM core: 256 threads, 8x8 per-thread register tile.
// As/Bs hold K-chunks of 32, stored [kk][row] with pad 132 (16B-aligned rows).
// ---------------------------------------------------------------------------
__device__ __forceinline__ void mma_tile(const float (*As)[PAD], const float (*Bs)[PAD],
                                         float acc[8][8], int ty, int tx) {
#pragma unroll
    for (int kk = 0; kk < 32; ++kk) {
        float4 a0 = *(const float4*)&As[kk][ty * 8];
        float4 a1 = *(const float4*)&As[kk][ty * 8 + 4];
        float4 b0 = *(const float4*)&Bs[kk][tx * 8];
        float4 b1 = *(const float4*)&Bs[kk][tx * 8 + 4];
        float a[8] = {a0.x, a0.y, a0.z, a0.w, a1.x, a1.y, a1.z, a1.w};
        float b[8] = {b0.x, b0.y, b0.z, b0.w, b1.x, b1.y, b1.z, b1.w};
#pragma unroll
        for (int i = 0; i < 8; ++i)
#pragma unroll
            for (int j = 0; j < 8; ++j)
                acc[i][j] = fmaf(a[i], b[j], acc[i][j]);
    }
}

// ---------------------------------------------------------------------------
// Kernel 0: zero BN accumulators
// ---------------------------------------------------------------------------
__global__ void zero_stats_kernel() {
    int t = threadIdx.x;
    if (t < C_) { g_sum[t] = 0.0f; g_sumsq[t] = 0.0f; }
}

// ---------------------------------------------------------------------------
// Kernel 1: QKV convs. grid (32 ntiles, 3 convs, 8 b)
//   conv 0: theta -> g_Q[b][n][ci]
//   conv 1: phi   -> 2x2 maxpool -> g_Kv[b][m][ci]
//   conv 2: g     -> 2x2 maxpool -> g_Vv[b][m][ci]
// A tile of 128 contiguous n = image rows (2*ntile, 2*ntile+1), so the 2x2
// pool pairs columns (j, j+1) within a thread and rows via shfl_xor(8).
// ---------------------------------------------------------------------------
__global__ void __launch_bounds__(256) qkv_kernel(
    const float* __restrict__ x,
    const float* __restrict__ theta_w, const float* __restrict__ theta_b,
    const float* __restrict__ phi_w,   const float* __restrict__ phi_b,
    const float* __restrict__ gw,      const float* __restrict__ gb) {
    __shared__ float As[32][PAD];
    __shared__ float Bs[32][PAD];
    const int ntile = blockIdx.x;
    const int conv  = blockIdx.y;
    const int b     = blockIdx.z;
    const float* w    = (conv == 0) ? theta_w : (conv == 1) ? phi_w : gw;
    const float* bias = (conv == 0) ? theta_b : (conv == 1) ? phi_b : gb;
    const int tid = threadIdx.x;
    const int ty = tid >> 4, tx = tid & 15;
    const int n0 = ntile * 128;
    const float* xb = x + (size_t)b * C_ * N_;

    float acc[8][8] = {};
    for (int c0 = 0; c0 < C_; c0 += 32) {
#pragma unroll
        for (int p = 0; p < 16; ++p) {           // As[kk][ci] = w[ci][c0+kk]
            int idx = p * 256 + tid;
            int ci = idx >> 5, kk = idx & 31;
            As[kk][ci] = w[ci * C_ + c0 + kk];
        }
#pragma unroll
        for (int p = 0; p < 16; ++p) {           // Bs[kk][n] = x[b][c0+kk][n0+n]
            int idx = p * 256 + tid;
            int n = idx & 127, kk = idx >> 7;
            Bs[kk][n] = xb[(size_t)(c0 + kk) * N_ + n0 + n];
        }
        __syncthreads();
        mma_tile(As, Bs, acc, ty, tx);
        __syncthreads();
    }

    float bv[8];
#pragma unroll
    for (int i = 0; i < 8; ++i) bv[i] = bias[ty * 8 + i];

    if (conv == 0) {
        // rows i = ci, cols j = n: store transposed to [n][ci]
#pragma unroll
        for (int j = 0; j < 8; ++j) {
            int n = n0 + tx * 8 + j;
            float* dst = &g_Q[((size_t)b * N_ + n) * CI_ + ty * 8];
            float4 v0 = make_float4(acc[0][j] + bv[0], acc[1][j] + bv[1],
                                    acc[2][j] + bv[2], acc[3][j] + bv[3]);
            float4 v1 = make_float4(acc[4][j] + bv[4], acc[5][j] + bv[5],
                                    acc[6][j] + bv[6], acc[7][j] + bv[7]);
            *(float4*)&dst[0] = v0;
            *(float4*)&dst[4] = v1;
        }
    } else {
        float* out = (conv == 1) ? g_Kv : g_Vv;
#pragma unroll
        for (int i = 0; i < 8; ++i) {
#pragma unroll
            for (int jj = 0; jj < 8; jj += 2) {
                float v = fmaxf(acc[i][jj], acc[i][jj + 1]);
                float p = __shfl_xor_sync(0xffffffffu, v, 8);
                v = fmaxf(v, p);
                if (tx < 8) {
                    int m = ntile * 32 + tx * 4 + (jj >> 1);
                    out[((size_t)b * M_ + m) * CI_ + ty * 8 + i] = v + bv[i];
                }
            }
        }
    }
}

// ---------------------------------------------------------------------------
// Kernel 2: S[b][n][m] = Q . K^T. grid (8 mtiles, 32 ntiles, 8 b)
// ---------------------------------------------------------------------------
__global__ void __launch_bounds__(256) scores_kernel() {
    __shared__ float As[32][PAD];
    __shared__ float Bs[32][PAD];
    const int mtile = blockIdx.x, ntile = blockIdx.y, b = blockIdx.z;
    const int tid = threadIdx.x;
    const int ty = tid >> 4, tx = tid & 15;

    float acc[8][8] = {};
    for (int k0 = 0; k0 < CI_; k0 += 32) {
#pragma unroll
        for (int p = 0; p < 16; ++p) {           // As[kk][i] = Q[b][n0+i][k0+kk]
            int idx = p * 256 + tid;
            int r = idx >> 5, kk = idx & 31;
            As[kk][r] = g_Q[((size_t)b * N_ + ntile * 128 + r) * CI_ + k0 + kk];
        }
#pragma unroll
        for (int p = 0; p < 16; ++p) {           // Bs[kk][j] = K[b][m0+j][k0+kk]
            int idx = p * 256 + tid;
            int r = idx >> 5, kk = idx & 31;
            Bs[kk][r] = g_Kv[((size_t)b * M_ + mtile * 128 + r) * CI_ + k0 + kk];
        }
        __syncthreads();
        mma_tile(As, Bs, acc, ty, tx);
        __syncthreads();
    }
#pragma unroll
    for (int i = 0; i < 8; ++i) {
        float* dst = &g_S[((size_t)b * N_ + ntile * 128 + ty * 8 + i) * M_ + mtile * 128 + tx * 8];
        *(float4*)&dst[0] = make_float4(acc[i][0], acc[i][1], acc[i][2], acc[i][3]);
        *(float4*)&dst[4] = make_float4(acc[i][4], acc[i][5], acc[i][6], acc[i][7]);
    }
}

// ---------------------------------------------------------------------------
// Kernel 3: row softmax over M_=1024. One warp per row, 8 rows per block.
// ---------------------------------------------------------------------------
__global__ void __launch_bounds__(256) softmax_kernel() {
    const int warp = threadIdx.x >> 5, lane = threadIdx.x & 31;
    const size_t row = (size_t)blockIdx.x * 8 + warp;
    float* S = g_S + row * M_;
    float v[32];
    float mx = -INFINITY;
#pragma unroll
    for (int i = 0; i < 32; ++i) { v[i] = S[lane + i * 32]; mx = fmaxf(mx, v[i]); }
#pragma unroll
    for (int o = 16; o > 0; o >>= 1) mx = fmaxf(mx, __shfl_xor_sync(0xffffffffu, mx, o));
    float s = 0.0f;
#pragma unroll
    for (int i = 0; i < 32; ++i) { v[i] = __expf(v[i] - mx); s += v[i]; }
#pragma unroll
    for (int o = 16; o > 0; o >>= 1) s += __shfl_xor_sync(0xffffffffu, s, o);
    const float inv = 1.0f / s;
#pragma unroll
    for (int i = 0; i < 32; ++i) S[lane + i * 32] = v[i] * inv;
}

// ---------------------------------------------------------------------------
// Kernel 4: Y[b][n][ci] = P . V. grid (32 ntiles, 8 b). K-dim = M_ = 1024.
// ---------------------------------------------------------------------------
__global__ void __launch_bounds__(256) pv_kernel() {
    __shared__ float As[32][PAD];
    __shared__ float Bs[32][PAD];
    const int ntile = blockIdx.x, b = blockIdx.y;
    const int tid = threadIdx.x;
    const int ty = tid >> 4, tx = tid & 15;

    float acc[8][8] = {};
    for (int k0 = 0; k0 < M_; k0 += 32) {
#pragma unroll
        for (int p = 0; p < 16; ++p) {           // As[kk][i] = P[b][n0+i][k0+kk]
            int idx = p * 256 + tid;
            int r = idx >> 5, kk = idx & 31;
            As[kk][r] = g_S[((size_t)b * N_ + ntile * 128 + r) * M_ + k0 + kk];
        }
#pragma unroll
        for (int p = 0; p < 16; ++p) {           // Bs[kk][j] = V[b][k0+kk][j]
            int idx = p * 256 + tid;
            int j = idx & 127, kk = idx >> 7;
            Bs[kk][j] = g_Vv[((size_t)b * M_ + k0 + kk) * CI_ + j];
        }
        __syncthreads();
        mma_tile(As, Bs, acc, ty, tx);
        __syncthreads();
    }
#pragma unroll
    for (int i = 0; i < 8; ++i) {
        float* dst = &g_Y[((size_t)b * N_ + ntile * 128 + ty * 8 + i) * CI_ + tx * 8];
        *(float4*)&dst[0] = make_float4(acc[i][0], acc[i][1], acc[i][2], acc[i][3]);
        *(float4*)&dst[4] = make_float4(acc[i][4], acc[i][5], acc[i][6], acc[i][7]);
    }
}

// ---------------------------------------------------------------------------
// Kernel 5: Wy[b][o][n] = W_w . Y + W_b, plus BN partial sums (atomic).
// grid (2 otiles, 32 ntiles, 8 b)
// ---------------------------------------------------------------------------
__global__ void __launch_bounds__(256) wy_kernel(const float* __restrict__ W_w,
                                                 const float* __restrict__ W_b) {
    __shared__ float As[32][PAD];
    __shared__ float Bs[32][PAD];
    const int otile = blockIdx.x, ntile = blockIdx.y, b = blockIdx.z;
    const int tid = threadIdx.x;
    const int ty = tid >> 4, tx = tid & 15;

    float acc[8][8] = {};
    for (int k0 = 0; k0 < CI_; k0 += 32) {
#pragma unroll
        for (int p = 0; p < 16; ++p) {           // As[kk][i] = W_w[o0+i][k0+kk]
            int idx = p * 256 + tid;
            int r = idx >> 5, kk = idx & 31;
            As[kk][r] = W_w[(size_t)(otile * 128 + r) * CI_ + k0 + kk];
        }
#pragma unroll
        for (int p = 0; p < 16; ++p) {           // Bs[kk][j] = Y[b][n0+j][k0+kk]
            int idx = p * 256 + tid;
            int r = idx >> 5, kk = idx & 31;
            Bs[kk][r] = g_Y[((size_t)b * N_ + ntile * 128 + r) * CI_ + k0 + kk];
        }
        __syncthreads();
        mma_tile(As, Bs, acc, ty, tx);
        __syncthreads();
    }

    float bv[8];
#pragma unroll
    for (int i = 0; i < 8; ++i) bv[i] = W_b[otile * 128 + ty * 8 + i];

    float srow[8], qrow[8];
#pragma unroll
    for (int i = 0; i < 8; ++i) {
        float s = 0.0f, q = 0.0f;
        float vals[8];
#pragma unroll
        for (int j = 0; j < 8; ++j) {
            float v = acc[i][j] + bv[i];
            vals[j] = v; s += v; q += v * v;
        }
        float* dst = &g_Wy[((size_t)(b * C_ + otile * 128 + ty * 8 + i)) * N_ + ntile * 128 + tx * 8];
        *(float4*)&dst[0] = make_float4(vals[0], vals[1], vals[2], vals[3]);
        *(float4*)&dst[4] = make_float4(vals[4], vals[5], vals[6], vals[7]);
        srow[i] = s; qrow[i] = q;
    }

    // block reduction across tx (16 threads per o row), then atomics
    __syncthreads();
    float* red = &As[0][0];   // 4224 floats available; use 4096
#pragma unroll
    for (int i = 0; i < 8; ++i) {
        red[(ty * 8 + i) * 16 + tx]        = srow[i];
        red[2048 + (ty * 8 + i) * 16 + tx] = qrow[i];
    }
    __syncthreads();
    if (tid < 128) {
        float ss = 0.0f, qq = 0.0f;
#pragma unroll
        for (int t = 0; t < 16; ++t) {
            ss += red[tid * 16 + t];
            qq += red[2048 + tid * 16 + t];
        }
        atomicAdd(&g_sum[otile * 128 + tid], ss);
        atomicAdd(&g_sumsq[otile * 128 + tid], qq);
    }
}

// ---------------------------------------------------------------------------
// Kernel 6: BN (batch stats) + gamma/beta + residual -> out
// ---------------------------------------------------------------------------
__global__ void __launch_bounds__(256) bn_out_kernel(const float* __restrict__ x,
                                                     const float* __restrict__ gamma,
                                                     const float* __restrict__ beta,
                                                     float* __restrict__ out) {
    const size_t idx = (size_t)blockIdx.x * 256 + threadIdx.x;   // total B*C*N = 8388608
    const int o = (int)((idx >> 12) & (C_ - 1));
    const float cnt_inv = 1.0f / (float)(B_ * N_);
    float mean = g_sum[o] * cnt_inv;
    float var  = g_sumsq[o] * cnt_inv - mean * mean;
    float inv  = rsqrtf(var + 1e-5f);
    out[idx] = (g_Wy[idx] - mean) * inv * gamma[o] + beta[o] + x[idx];
}

// ---------------------------------------------------------------------------
extern "C" void kernel_launch(void* const* d_in, const int* in_sizes, int n_in,
                              void* d_out, int out_size) {
    const float* x       = (const float*)d_in[0];
    const float* theta_w = (const float*)d_in[1];
    const float* theta_b = (const float*)d_in[2];
    const float* phi_w   = (const float*)d_in[3];
    const float* phi_b   = (const float*)d_in[4];
    const float* gw      = (const float*)d_in[5];
    const float* gb      = (const float*)d_in[6];
    const float* W_w     = (const float*)d_in[7];
    const float* W_b     = (const float*)d_in[8];
    const float* gamma   = (const float*)d_in[9];
    const float* beta    = (const float*)d_in[10];
    float* out = (float*)d_out;

    zero_stats_kernel<<<1, 256>>>();
    qkv_kernel<<<dim3(32, 3, 8), 256>>>(x, theta_w, theta_b, phi_w, phi_b, gw, gb);
    scores_kernel<<<dim3(8, 32, 8), 256>>>();
    softmax_kernel<<<4096, 256>>>();
    pv_kernel<<<dim3(32, 8), 256>>>();
    wy_kernel<<<dim3(2, 32, 8), 256>>>(W_w, W_b);
    bn_out_kernel<<<32768, 256>>>(x, gamma, beta, out);
}

// round 4
// speedup vs baseline: 1.2534x; 1.2534x over previous
#include <cuda_runtime.h>
#include <cuda_bf16.h>
#include <mma.h>
#include <cstdint>
#include <math.h>

#define B_   8
#define C_   256
#define CI_  128
#define N_   4096
#define M_   1024

using bf16 = __nv_bfloat16;
namespace wm = nvcuda::wmma;

// ---------------------------------------------------------------------------
// Scratch (device globals; allocation-free)
// ---------------------------------------------------------------------------
__device__ __align__(16) bf16 g_xT_h[(size_t)B_*N_*C_];
__device__ __align__(16) bf16 g_xT_l[(size_t)B_*N_*C_];
__device__ __align__(16) bf16 g_w3_h[3*CI_*C_];
__device__ __align__(16) bf16 g_w3_l[3*CI_*C_];
__device__ __align__(16) bf16 g_Ww_h[C_*CI_];
__device__ __align__(16) bf16 g_Ww_l[C_*CI_];
__device__ __align__(16) bf16 g_Q_h[(size_t)B_*N_*CI_];
__device__ __align__(16) bf16 g_Q_l[(size_t)B_*N_*CI_];
__device__ __align__(16) bf16 g_K_h[(size_t)B_*M_*CI_];
__device__ __align__(16) bf16 g_K_l[(size_t)B_*M_*CI_];
__device__ __align__(16) bf16 g_Vt_h[(size_t)B_*CI_*M_];
__device__ __align__(16) bf16 g_Vt_l[(size_t)B_*CI_*M_];
__device__ __align__(16) float g_S  [(size_t)B_*N_*M_];
__device__ __align__(16) bf16 g_P_h[(size_t)B_*N_*M_];
__device__ __align__(16) bf16 g_P_l[(size_t)B_*N_*M_];
__device__ __align__(16) bf16 g_Y_h[(size_t)B_*N_*CI_];
__device__ __align__(16) bf16 g_Y_l[(size_t)B_*N_*CI_];
__device__ __align__(16) float g_Wy [(size_t)B_*C_*N_];
__device__ float g_sum[C_], g_sumsq[C_];

// ---------------------------------------------------------------------------
// Helpers
// ---------------------------------------------------------------------------
__device__ __forceinline__ uint32_t smem_u32(const void* p) {
    uint32_t a;
    asm("{ .reg .u64 t; cvta.to.shared.u64 t, %1; cvt.u32.u64 %0, t; }" : "=r"(a) : "l"(p));
    return a;
}
#define CP16(d, s)  asm volatile("cp.async.cg.shared.global [%0], [%1], 16;" :: "r"(d), "l"(s))
#define CPCOMMIT()  asm volatile("cp.async.commit_group;" ::: "memory")
#define CPWAIT0()   asm volatile("cp.async.wait_group 0;" ::: "memory")

__device__ __forceinline__ void split_bf16(float v, bf16& h, bf16& l) {
    h = __float2bfloat16(v);
    l = __float2bfloat16(v - __bfloat162float(h));
}

// ---------------------------------------------------------------------------
// Shared 128x128 GEMM core (split-bf16, 3 MMA products, cp.async 2-stage)
// Result left in shared fp32 tile T (row stride TSTR).
// ---------------------------------------------------------------------------
#define TSTR 132
#define TILE_BYTES  10240          // 128 rows x 40 bf16 (pad) x 2B
#define STAGE_BYTES (4*TILE_BYTES) // Ah, Al, Bh, Bl
#define SMEM_BYTES  (2*STAGE_BYTES)  // 81920; fp32 T (128*132*4=67584) reuses it

__device__ __forceinline__ void gemm_tile(char* smem, uint32_t sb,
        const bf16* __restrict__ Ah, const bf16* __restrict__ Al, int strA,
        const bf16* __restrict__ Bh, const bf16* __restrict__ Bl, int strB,
        int kchunks) {
    const int tid = threadIdx.x;
    const int wid = tid >> 5;
    const int wmi = wid >> 2;      // 0..1 : 64 rows each
    const int wni = wid & 3;       // 0..3 : 32 cols each

    wm::fragment<wm::accumulator, 16, 16, 16, float> acc[4][2];
#pragma unroll
    for (int fm = 0; fm < 4; ++fm)
#pragma unroll
        for (int fn = 0; fn < 2; ++fn)
            wm::fill_fragment(acc[fm][fn], 0.0f);

    auto issue = [&](int kc, int s) {
        const bf16* srcs[4] = { Ah + kc * 32, Al + kc * 32, Bh + kc * 32, Bl + kc * 32 };
#pragma unroll
        for (int t = 0; t < 4; ++t) {
            const int str = (t < 2) ? strA : strB;
            const bf16* base = srcs[t];
            const uint32_t dbase = sb + s * STAGE_BYTES + t * TILE_BYTES;
#pragma unroll
            for (int i = 0; i < 2; ++i) {
                int idx = i * 256 + tid;       // 512 chunks of 16B
                int r = idx >> 2, c = idx & 3;
                CP16(dbase + r * 80 + c * 16, base + (size_t)r * str + c * 8);
            }
        }
        CPCOMMIT();
    };

    issue(0, 0);
    for (int kc = 0; kc < kchunks; ++kc) {
        CPWAIT0();
        __syncthreads();
        if (kc + 1 < kchunks) issue(kc + 1, (kc + 1) & 1);
        const bf16* sAh = (const bf16*)(smem + (kc & 1) * STAGE_BYTES);
        const bf16* sAl = sAh + 5120;
        const bf16* sBh = sAh + 10240;
        const bf16* sBl = sAh + 15360;
#pragma unroll
        for (int kk = 0; kk < 32; kk += 16) {
            wm::fragment<wm::matrix_a, 16, 16, 16, bf16, wm::row_major> ah[4], al[4];
            wm::fragment<wm::matrix_b, 16, 16, 16, bf16, wm::col_major> bh[2], bl[2];
#pragma unroll
            for (int f = 0; f < 4; ++f) {
                wm::load_matrix_sync(ah[f], sAh + (wmi * 64 + f * 16) * 40 + kk, 40);
                wm::load_matrix_sync(al[f], sAl + (wmi * 64 + f * 16) * 40 + kk, 40);
            }
#pragma unroll
            for (int f = 0; f < 2; ++f) {
                wm::load_matrix_sync(bh[f], sBh + (wni * 32 + f * 16) * 40 + kk, 40);
                wm::load_matrix_sync(bl[f], sBl + (wni * 32 + f * 16) * 40 + kk, 40);
            }
#pragma unroll
            for (int fm = 0; fm < 4; ++fm)
#pragma unroll
                for (int fn = 0; fn < 2; ++fn) {
                    wm::mma_sync(acc[fm][fn], ah[fm], bh[fn], acc[fm][fn]);
                    wm::mma_sync(acc[fm][fn], ah[fm], bl[fn], acc[fm][fn]);
                    wm::mma_sync(acc[fm][fn], al[fm], bh[fn], acc[fm][fn]);
                }
        }
    }
    __syncthreads();                       // all warps done reading stages
    float* T = (float*)smem;
#pragma unroll
    for (int fm = 0; fm < 4; ++fm)
#pragma unroll
        for (int fn = 0; fn < 2; ++fn)
            wm::store_matrix_sync(T + (wmi * 64 + fm * 16) * TSTR + wni * 32 + fn * 16,
                                  acc[fm][fn], TSTR, wm::mem_row_major);
    __syncthreads();
}

// ---------------------------------------------------------------------------
// Prep kernels
// ---------------------------------------------------------------------------
__global__ void __launch_bounds__(256) cvt_weights(
    const float* __restrict__ tw, const float* __restrict__ pw,
    const float* __restrict__ gw, const float* __restrict__ ww) {
    int i = blockIdx.x * 256 + threadIdx.x;      // 32768 threads
    bf16 h, l;
    split_bf16(tw[i], h, l); g_w3_h[i] = h;           g_w3_l[i] = l;
    split_bf16(pw[i], h, l); g_w3_h[32768 + i] = h;   g_w3_l[32768 + i] = l;
    split_bf16(gw[i], h, l); g_w3_h[65536 + i] = h;   g_w3_l[65536 + i] = l;
    split_bf16(ww[i], h, l); g_Ww_h[i] = h;           g_Ww_l[i] = l;
}

__global__ void __launch_bounds__(256) xT_kernel(const float* __restrict__ x) {
    __shared__ float t[32][33];
    int n0 = blockIdx.x * 32, c0 = blockIdx.y * 32, b = blockIdx.z;
    int j = threadIdx.x & 31, r = threadIdx.x >> 5;
    const float* xb = x + ((size_t)b * C_ + c0) * N_ + n0;
#pragma unroll
    for (int rr = 0; rr < 32; rr += 8)
        t[r + rr][j] = xb[(size_t)(r + rr) * N_ + j];
    __syncthreads();
#pragma unroll
    for (int rr = 0; rr < 32; rr += 8) {
        float v = t[j][r + rr];
        bf16 h, l; split_bf16(v, h, l);
        size_t o = ((size_t)b * N_ + n0 + r + rr) * C_ + c0 + j;
        g_xT_h[o] = h; g_xT_l[o] = l;
    }
}

__global__ void zero_stats_kernel() {
    int t = threadIdx.x;
    if (t < C_) { g_sum[t] = 0.0f; g_sumsq[t] = 0.0f; }
}

// ---------------------------------------------------------------------------
// GEMM kernels
// ---------------------------------------------------------------------------
// QKV conv: T[ci][n] = w . xT^T (K=256). conv1/2 add in-tile 2x2 maxpool.
__global__ void __launch_bounds__(256) qkv_mma(
    const float* __restrict__ tb, const float* __restrict__ pb,
    const float* __restrict__ gbias) {
    extern __shared__ char smem[];
    uint32_t sb = smem_u32(smem);
    int nt = blockIdx.x, conv = blockIdx.y, b = blockIdx.z;
    const bf16* Ah = g_w3_h + conv * (CI_ * C_);
    const bf16* Al = g_w3_l + conv * (CI_ * C_);
    const bf16* Bh = g_xT_h + ((size_t)b * N_ + nt * 128) * C_;
    const bf16* Bl = g_xT_l + ((size_t)b * N_ + nt * 128) * C_;
    gemm_tile(smem, sb, Ah, Al, C_, Bh, Bl, C_, 8);

    const float* T = (const float*)smem;
    const float* bias = (conv == 0) ? tb : (conv == 1) ? pb : gbias;
    int tid = threadIdx.x;

    if (conv == 0) {
        // transpose: thread owns column n, writes contiguous ci runs
        int n = tid & 127, h = tid >> 7;
        size_t base = ((size_t)b * N_ + nt * 128 + n) * CI_;
#pragma unroll
        for (int c8 = 0; c8 < 8; ++c8) {
            int ci0 = h * 64 + c8 * 8;
            __align__(16) bf16 hs[8], ls[8];
#pragma unroll
            for (int q = 0; q < 8; ++q) {
                float v = T[(ci0 + q) * TSTR + n] + bias[ci0 + q];
                split_bf16(v, hs[q], ls[q]);
            }
            *(uint4*)&g_Q_h[base + ci0] = *(const uint4*)hs;
            *(uint4*)&g_Q_l[base + ci0] = *(const uint4*)ls;
        }
    } else if (conv == 1) {
        // maxpool -> K[m][ci]: thread owns m-col c, writes 16 contiguous ci
        int c = tid & 31, h = tid >> 5;          // h in 0..7
        int m = nt * 32 + c;
        size_t base = ((size_t)b * M_ + m) * CI_ + h * 16;
        __align__(16) bf16 hs[16], ls[16];
#pragma unroll
        for (int q = 0; q < 16; ++q) {
            int ci = h * 16 + q;
            const float* row = &T[ci * TSTR];
            float v = fmaxf(fmaxf(row[2 * c], row[2 * c + 1]),
                            fmaxf(row[64 + 2 * c], row[65 + 2 * c])) + bias[ci];
            split_bf16(v, hs[q], ls[q]);
        }
        *(uint4*)&g_K_h[base]     = *(const uint4*)hs;
        *(uint4*)&g_K_h[base + 8] = *(const uint4*)(hs + 8);
        *(uint4*)&g_K_l[base]     = *(const uint4*)ls;
        *(uint4*)&g_K_l[base + 8] = *(const uint4*)(ls + 8);
    } else {
        // maxpool -> Vt[ci][m]: thread owns ci row, writes 16 contiguous m
        int ci = tid & 127, h = tid >> 7;        // h in 0..1
        const float* row = &T[ci * TSTR];
        float bv = bias[ci];
        size_t base = ((size_t)b * CI_ + ci) * M_ + nt * 32 + h * 16;
        __align__(16) bf16 hs[16], ls[16];
#pragma unroll
        for (int q = 0; q < 16; ++q) {
            int c = h * 16 + q;
            float v = fmaxf(fmaxf(row[2 * c], row[2 * c + 1]),
                            fmaxf(row[64 + 2 * c], row[65 + 2 * c])) + bv;
            split_bf16(v, hs[q], ls[q]);
        }
        *(uint4*)&g_Vt_h[base]     = *(const uint4*)hs;
        *(uint4*)&g_Vt_h[base + 8] = *(const uint4*)(hs + 8);
        *(uint4*)&g_Vt_l[base]     = *(const uint4*)ls;
        *(uint4*)&g_Vt_l[base + 8] = *(const uint4*)(ls + 8);
    }
}

// Scores: T[n][m] = Q . K^T (K=128)
__global__ void __launch_bounds__(256) scores_mma() {
    extern __shared__ char smem[];
    uint32_t sb = smem_u32(smem);
    int mt = blockIdx.x, nt = blockIdx.y, b = blockIdx.z;
    const bf16* Ah = g_Q_h + ((size_t)b * N_ + nt * 128) * CI_;
    const bf16* Al = g_Q_l + ((size_t)b * N_ + nt * 128) * CI_;
    const bf16* Bh = g_K_h + ((size_t)b * M_ + mt * 128) * CI_;
    const bf16* Bl = g_K_l + ((size_t)b * M_ + mt * 128) * CI_;
    gemm_tile(smem, sb, Ah, Al, CI_, Bh, Bl, CI_, 4);

    const float* T = (const float*)smem;
    int tid = threadIdx.x;
    int n = tid & 127, h = tid >> 7;
    float* row = g_S + ((size_t)b * N_ + nt * 128 + n) * M_ + mt * 128 + h * 64;
    const float* src = &T[n * TSTR + h * 64];
#pragma unroll
    for (int q = 0; q < 16; ++q)
        *(float4*)(row + 4 * q) = make_float4(src[4 * q], src[4 * q + 1],
                                              src[4 * q + 2], src[4 * q + 3]);
}

// Softmax rows of 1024 -> split-bf16 P
__global__ void __launch_bounds__(256) softmax_kernel() {
    const int warp = threadIdx.x >> 5, lane = threadIdx.x & 31;
    const size_t row = (size_t)blockIdx.x * 8 + warp;
    const float* S = g_S + row * M_;
    bf16* Ph = g_P_h + row * M_;
    bf16* Pl = g_P_l + row * M_;
    float v[32];
    float mx = -INFINITY;
#pragma unroll
    for (int i = 0; i < 32; ++i) { v[i] = S[lane + i * 32]; mx = fmaxf(mx, v[i]); }
#pragma unroll
    for (int o = 16; o > 0; o >>= 1) mx = fmaxf(mx, __shfl_xor_sync(0xffffffffu, mx, o));
    float s = 0.0f;
#pragma unroll
    for (int i = 0; i < 32; ++i) { v[i] = __expf(v[i] - mx); s += v[i]; }
#pragma unroll
    for (int o = 16; o > 0; o >>= 1) s += __shfl_xor_sync(0xffffffffu, s, o);
    const float inv = 1.0f / s;
#pragma unroll
    for (int i = 0; i < 32; ++i) {
        float p = v[i] * inv;
        bf16 h, l; split_bf16(p, h, l);
        Ph[lane + i * 32] = h; Pl[lane + i * 32] = l;
    }
}

// PV: T[n][ci] = P . Vt^T (K=1024)
__global__ void __launch_bounds__(256) pv_mma() {
    extern __shared__ char smem[];
    uint32_t sb = smem_u32(smem);
    int nt = blockIdx.x, b = blockIdx.y;
    const bf16* Ah = g_P_h + ((size_t)b * N_ + nt * 128) * M_;
    const bf16* Al = g_P_l + ((size_t)b * N_ + nt * 128) * M_;
    const bf16* Bh = g_Vt_h + (size_t)b * CI_ * M_;
    const bf16* Bl = g_Vt_l + (size_t)b * CI_ * M_;
    gemm_tile(smem, sb, Ah, Al, M_, Bh, Bl, M_, 32);

    const float* T = (const float*)smem;
    int tid = threadIdx.x;
    int n = tid & 127, h = tid >> 7;
    size_t base = ((size_t)b * N_ + nt * 128 + n) * CI_;
    const float* src = &T[n * TSTR];
#pragma unroll
    for (int c8 = 0; c8 < 8; ++c8) {
        int ci0 = h * 64 + c8 * 8;
        __align__(16) bf16 hs[8], ls[8];
#pragma unroll
        for (int q = 0; q < 8; ++q)
            split_bf16(src[ci0 + q], hs[q], ls[q]);
        *(uint4*)&g_Y_h[base + ci0] = *(const uint4*)hs;
        *(uint4*)&g_Y_l[base + ci0] = *(const uint4*)ls;
    }
}

// Wy: T[o][n] = Ww . Y^T + b (K=128), plus BN partial sums
__global__ void __launch_bounds__(256) wy_mma(const float* __restrict__ Wb) {
    extern __shared__ char smem[];
    uint32_t sb = smem_u32(smem);
    int ot = blockIdx.x, nt = blockIdx.y, b = blockIdx.z;
    const bf16* Ah = g_Ww_h + (size_t)ot * 128 * CI_;
    const bf16* Al = g_Ww_l + (size_t)ot * 128 * CI_;
    const bf16* Bh = g_Y_h + ((size_t)b * N_ + nt * 128) * CI_;
    const bf16* Bl = g_Y_l + ((size_t)b * N_ + nt * 128) * CI_;
    gemm_tile(smem, sb, Ah, Al, CI_, Bh, Bl, CI_, 4);

    const float* T = (const float*)smem;
    int tid = threadIdx.x;
    int o = tid & 127, h = tid >> 7;
    float bv = Wb[ot * 128 + o];
    float* row = g_Wy + ((size_t)(b * C_ + ot * 128 + o)) * N_ + nt * 128 + h * 64;
    const float* src = &T[o * TSTR + h * 64];
    float s = 0.0f, q = 0.0f;
#pragma unroll
    for (int qd = 0; qd < 16; ++qd) {
        float v0 = src[4 * qd]     + bv;
        float v1 = src[4 * qd + 1] + bv;
        float v2 = src[4 * qd + 2] + bv;
        float v3 = src[4 * qd + 3] + bv;
        *(float4*)(row + 4 * qd) = make_float4(v0, v1, v2, v3);
        s += v0 + v1 + v2 + v3;
        q += v0 * v0 + v1 * v1 + v2 * v2 + v3 * v3;
    }
    atomicAdd(&g_sum[ot * 128 + o], s);
    atomicAdd(&g_sumsq[ot * 128 + o], q);
}

// BN + gamma/beta + residual
__global__ void __launch_bounds__(256) bn_out_kernel(const float* __restrict__ x,
                                                     const float* __restrict__ gamma,
                                                     const float* __restrict__ beta,
                                                     float* __restrict__ out) {
    const size_t idx = (size_t)blockIdx.x * 256 + threadIdx.x;
    const int o = (int)((idx >> 12) & (C_ - 1));
    const float cnt_inv = 1.0f / (float)(B_ * N_);
    float mean = g_sum[o] * cnt_inv;
    float var  = g_sumsq[o] * cnt_inv - mean * mean;
    float inv  = rsqrtf(var + 1e-5f);
    out[idx] = (g_Wy[idx] - mean) * inv * gamma[o] + beta[o] + x[idx];
}

// ---------------------------------------------------------------------------
extern "C" void kernel_launch(void* const* d_in, const int* in_sizes, int n_in,
                              void* d_out, int out_size) {
    const float* x       = (const float*)d_in[0];
    const float* theta_w = (const float*)d_in[1];
    const float* theta_b = (const float*)d_in[2];
    const float* phi_w   = (const float*)d_in[3];
    const float* phi_b   = (const float*)d_in[4];
    const float* gw      = (const float*)d_in[5];
    const float* gb      = (const float*)d_in[6];
    const float* W_w     = (const float*)d_in[7];
    const float* W_b     = (const float*)d_in[8];
    const float* gamma   = (const float*)d_in[9];
    const float* beta    = (const float*)d_in[10];
    float* out = (float*)d_out;

    static bool attr_done = false;
    if (!attr_done) {
        cudaFuncSetAttribute(qkv_mma,    cudaFuncAttributeMaxDynamicSharedMemorySize, SMEM_BYTES);
        cudaFuncSetAttribute(scores_mma, cudaFuncAttributeMaxDynamicSharedMemorySize, SMEM_BYTES);
        cudaFuncSetAttribute(pv_mma,     cudaFuncAttributeMaxDynamicSharedMemorySize, SMEM_BYTES);
        cudaFuncSetAttribute(wy_mma,     cudaFuncAttributeMaxDynamicSharedMemorySize, SMEM_BYTES);
        attr_done = true;
    }

    cvt_weights<<<128, 256>>>(theta_w, phi_w, gw, W_w);
    xT_kernel<<<dim3(128, 8, 8), 256>>>(x);
    zero_stats_kernel<<<1, 256>>>();
    qkv_mma<<<dim3(32, 3, 8), 256, SMEM_BYTES>>>(theta_b, phi_b, gb);
    scores_mma<<<dim3(8, 32, 8), 256, SMEM_BYTES>>>();
    softmax_kernel<<<4096, 256>>>();
    pv_mma<<<dim3(32, 8), 256, SMEM_BYTES>>>();
    wy_mma<<<dim3(2, 32, 8), 256, SMEM_BYTES>>>(W_b);
    bn_out_kernel<<<32768, 256>>>(x, gamma, beta, out);
}

// round 6
// speedup vs baseline: 1.7899x; 1.4280x over previous
#include <cuda_runtime.h>
#include <cuda_bf16.h>
#include <mma.h>
#include <cstdint>
#include <math.h>

#define B_   8
#define C_   256
#define CI_  128
#define N_   4096
#define M_   1024

using bf16 = __nv_bfloat16;
namespace wm = nvcuda::wmma;

// ---------------------------------------------------------------------------
// Scratch (device globals; allocation-free)
// ---------------------------------------------------------------------------
__device__ __align__(16) bf16 g_xT_h[(size_t)B_*N_*C_];
__device__ __align__(16) bf16 g_xT_l[(size_t)B_*N_*C_];
__device__ __align__(16) bf16 g_w3_h[3*CI_*C_];
__device__ __align__(16) bf16 g_w3_l[3*CI_*C_];
__device__ __align__(16) bf16 g_Ww_h[C_*CI_];
__device__ __align__(16) bf16 g_Ww_l[C_*CI_];
__device__ __align__(16) bf16 g_Q_h[(size_t)B_*N_*CI_];
__device__ __align__(16) bf16 g_Q_l[(size_t)B_*N_*CI_];
__device__ __align__(16) bf16 g_K_h[(size_t)B_*M_*CI_];
__device__ __align__(16) bf16 g_K_l[(size_t)B_*M_*CI_];
__device__ __align__(16) bf16 g_Vt_h[(size_t)B_*CI_*M_];
__device__ __align__(16) bf16 g_Vt_l[(size_t)B_*CI_*M_];
__device__ __align__(16) float g_S  [(size_t)B_*N_*M_];
__device__ __align__(16) bf16 g_P_h[(size_t)B_*N_*M_];
__device__ __align__(16) bf16 g_P_l[(size_t)B_*N_*M_];
__device__ __align__(16) bf16 g_Y_h[(size_t)B_*N_*CI_];
__device__ __align__(16) bf16 g_Y_l[(size_t)B_*N_*CI_];
__device__ __align__(16) float g_Wy [(size_t)B_*C_*N_];
__device__ float g_sum[C_], g_sumsq[C_];

// ---------------------------------------------------------------------------
// Helpers
// ---------------------------------------------------------------------------
__device__ __forceinline__ uint32_t smem_u32(const void* p) {
    uint32_t a;
    asm("{ .reg .u64 t; cvta.to.shared.u64 t, %1; cvt.u32.u64 %0, t; }" : "=r"(a) : "l"(p));
    return a;
}
#define CP16(d, s)  asm volatile("cp.async.cg.shared.global [%0], [%1], 16;" :: "r"(d), "l"(s))
#define CPCOMMIT()  asm volatile("cp.async.commit_group;" ::: "memory")
#define CPWAIT0()   asm volatile("cp.async.wait_group 0;" ::: "memory")

__device__ __forceinline__ void split_bf16(float v, bf16& h, bf16& l) {
    h = __float2bfloat16(v);
    l = __float2bfloat16(v - __bfloat162float(h));
}

// ---------------------------------------------------------------------------
// Shared 128x128 GEMM core (split-bf16, 3 MMA products, cp.async 2-stage)
// 512 threads, 16 warps, warp tile 64x16 (4x1 fragments).
// Result left in shared fp32 tile T (row stride TSTR).
// ---------------------------------------------------------------------------
#define TSTR 132
#define TILE_BYTES  10240          // 128 rows x 40 bf16 (pad) x 2B
#define STAGE_BYTES (4*TILE_BYTES) // Ah, Al, Bh, Bl
#define SMEM_BYTES  (2*STAGE_BYTES)  // 81920; fp32 T (128*132*4=67584) reuses it
#define NTHREADS 512

__device__ __forceinline__ void gemm_tile(char* smem, uint32_t sb,
        const bf16* __restrict__ Ah, const bf16* __restrict__ Al, int strA,
        const bf16* __restrict__ Bh, const bf16* __restrict__ Bl, int strB,
        int kchunks) {
    const int tid = threadIdx.x;
    const int wid = tid >> 5;
    const int wmi = wid >> 3;      // 0..1 : 64 rows each
    const int wni = wid & 7;       // 0..7 : 16 cols each

    wm::fragment<wm::accumulator, 16, 16, 16, float> acc[4];
#pragma unroll
    for (int fm = 0; fm < 4; ++fm)
        wm::fill_fragment(acc[fm], 0.0f);

    const int r = tid >> 2, c = tid & 3;   // 128 rows x 4 16B-chunks
    auto issue = [&](int kc, int s) {
        const bf16* srcs[4] = { Ah + kc * 32, Al + kc * 32, Bh + kc * 32, Bl + kc * 32 };
#pragma unroll
        for (int t = 0; t < 4; ++t) {
            const int str = (t < 2) ? strA : strB;
            CP16(sb + s * STAGE_BYTES + t * TILE_BYTES + r * 80 + c * 16,
                 srcs[t] + (size_t)r * str + c * 8);
        }
        CPCOMMIT();
    };

    issue(0, 0);
    for (int kc = 0; kc < kchunks; ++kc) {
        CPWAIT0();
        __syncthreads();
        if (kc + 1 < kchunks) issue(kc + 1, (kc + 1) & 1);
        const bf16* sAh = (const bf16*)(smem + (kc & 1) * STAGE_BYTES);
        const bf16* sAl = sAh + 5120;
        const bf16* sBh = sAh + 10240;
        const bf16* sBl = sAh + 15360;
#pragma unroll
        for (int kk = 0; kk < 32; kk += 16) {
            wm::fragment<wm::matrix_a, 16, 16, 16, bf16, wm::row_major> ah[4], al[4];
            wm::fragment<wm::matrix_b, 16, 16, 16, bf16, wm::col_major> bh, bl;
#pragma unroll
            for (int f = 0; f < 4; ++f) {
                wm::load_matrix_sync(ah[f], sAh + (wmi * 64 + f * 16) * 40 + kk, 40);
                wm::load_matrix_sync(al[f], sAl + (wmi * 64 + f * 16) * 40 + kk, 40);
            }
            wm::load_matrix_sync(bh, sBh + (wni * 16) * 40 + kk, 40);
            wm::load_matrix_sync(bl, sBl + (wni * 16) * 40 + kk, 40);
#pragma unroll
            for (int fm = 0; fm < 4; ++fm) {
                wm::mma_sync(acc[fm], ah[fm], bh, acc[fm]);
                wm::mma_sync(acc[fm], ah[fm], bl, acc[fm]);
                wm::mma_sync(acc[fm], al[fm], bh, acc[fm]);
            }
        }
    }
    __syncthreads();                       // all warps done reading stages
    float* T = (float*)smem;
#pragma unroll
    for (int fm = 0; fm < 4; ++fm)
        wm::store_matrix_sync(T + (wmi * 64 + fm * 16) * TSTR + wni * 16,
                              acc[fm], TSTR, wm::mem_row_major);
    __syncthreads();
}

// ---------------------------------------------------------------------------
// Prep kernels
// ---------------------------------------------------------------------------
__global__ void __launch_bounds__(256) cvt_weights(
    const float* __restrict__ tw, const float* __restrict__ pw,
    const float* __restrict__ gw, const float* __restrict__ ww) {
    int i = blockIdx.x * 256 + threadIdx.x;      // 32768 threads
    bf16 h, l;
    split_bf16(tw[i], h, l); g_w3_h[i] = h;           g_w3_l[i] = l;
    split_bf16(pw[i], h, l); g_w3_h[32768 + i] = h;   g_w3_l[32768 + i] = l;
    split_bf16(gw[i], h, l); g_w3_h[65536 + i] = h;   g_w3_l[65536 + i] = l;
    split_bf16(ww[i], h, l); g_Ww_h[i] = h;           g_Ww_l[i] = l;
}

__global__ void __launch_bounds__(256) xT_kernel(const float* __restrict__ x) {
    __shared__ float t[32][33];
    int n0 = blockIdx.x * 32, c0 = blockIdx.y * 32, b = blockIdx.z;
    int j = threadIdx.x & 31, r = threadIdx.x >> 5;
    const float* xb = x + ((size_t)b * C_ + c0) * N_ + n0;
#pragma unroll
    for (int rr = 0; rr < 32; rr += 8)
        t[r + rr][j] = xb[(size_t)(r + rr) * N_ + j];
    __syncthreads();
#pragma unroll
    for (int rr = 0; rr < 32; rr += 8) {
        float v = t[j][r + rr];
        bf16 h, l; split_bf16(v, h, l);
        size_t o = ((size_t)b * N_ + n0 + r + rr) * C_ + c0 + j;
        g_xT_h[o] = h; g_xT_l[o] = l;
    }
}

__global__ void zero_stats_kernel() {
    int t = threadIdx.x;
    if (t < C_) { g_sum[t] = 0.0f; g_sumsq[t] = 0.0f; }
}

// ---------------------------------------------------------------------------
// GEMM kernels (512 threads each)
// ---------------------------------------------------------------------------
// QKV conv: T[ci][n] = w . xT^T (K=256). conv1/2 add in-tile 2x2 maxpool.
__global__ void __launch_bounds__(NTHREADS) qkv_mma(
    const float* __restrict__ tb, const float* __restrict__ pb,
    const float* __restrict__ gbias) {
    extern __shared__ char smem[];
    uint32_t sb = smem_u32(smem);
    int nt = blockIdx.x, conv = blockIdx.y, b = blockIdx.z;
    const bf16* Ah = g_w3_h + conv * (CI_ * C_);
    const bf16* Al = g_w3_l + conv * (CI_ * C_);
    const bf16* Bh = g_xT_h + ((size_t)b * N_ + nt * 128) * C_;
    const bf16* Bl = g_xT_l + ((size_t)b * N_ + nt * 128) * C_;
    gemm_tile(smem, sb, Ah, Al, C_, Bh, Bl, C_, 8);

    const float* T = (const float*)smem;
    const float* bias = (conv == 0) ? tb : (conv == 1) ? pb : gbias;
    int tid = threadIdx.x;

    if (conv == 0) {
        // transpose: thread owns column n, writes contiguous ci runs
        int n = tid & 127, h = tid >> 7;     // h in 0..3
        size_t base = ((size_t)b * N_ + nt * 128 + n) * CI_;
#pragma unroll
        for (int c8 = 0; c8 < 4; ++c8) {
            int ci0 = h * 32 + c8 * 8;
            __align__(16) bf16 hs[8], ls[8];
#pragma unroll
            for (int q = 0; q < 8; ++q) {
                float v = T[(ci0 + q) * TSTR + n] + bias[ci0 + q];
                split_bf16(v, hs[q], ls[q]);
            }
            *(uint4*)&g_Q_h[base + ci0] = *(const uint4*)hs;
            *(uint4*)&g_Q_l[base + ci0] = *(const uint4*)ls;
        }
    } else if (conv == 1) {
        // maxpool -> K[m][ci]: thread owns m-col c, writes 8 contiguous ci
        int c = tid & 31, h = tid >> 5;      // h in 0..15
        int m = nt * 32 + c;
        size_t base = ((size_t)b * M_ + m) * CI_ + h * 8;
        __align__(16) bf16 hs[8], ls[8];
#pragma unroll
        for (int q = 0; q < 8; ++q) {
            int ci = h * 8 + q;
            const float* row = &T[ci * TSTR];
            float v = fmaxf(fmaxf(row[2 * c], row[2 * c + 1]),
                            fmaxf(row[64 + 2 * c], row[65 + 2 * c])) + bias[ci];
            split_bf16(v, hs[q], ls[q]);
        }
        *(uint4*)&g_K_h[base] = *(const uint4*)hs;
        *(uint4*)&g_K_l[base] = *(const uint4*)ls;
    } else {
        // maxpool -> Vt[ci][m]: thread owns ci row, writes 8 contiguous m
        int ci = tid & 127, h = tid >> 7;    // h in 0..3
        const float* row = &T[ci * TSTR];
        float bv = bias[ci];
        size_t base = ((size_t)b * CI_ + ci) * M_ + nt * 32 + h * 8;
        __align__(16) bf16 hs[8], ls[8];
#pragma unroll
        for (int q = 0; q < 8; ++q) {
            int c = h * 8 + q;
            float v = fmaxf(fmaxf(row[2 * c], row[2 * c + 1]),
                            fmaxf(row[64 + 2 * c], row[65 + 2 * c])) + bv;
            split_bf16(v, hs[q], ls[q]);
        }
        *(uint4*)&g_Vt_h[base] = *(const uint4*)hs;
        *(uint4*)&g_Vt_l[base] = *(const uint4*)ls;
    }
}

// Scores: T[n][m] = Q . K^T (K=128)
__global__ void __launch_bounds__(NTHREADS) scores_mma() {
    extern __shared__ char smem[];
    uint32_t sb = smem_u32(smem);
    int mt = blockIdx.x, nt = blockIdx.y, b = blockIdx.z;
    const bf16* Ah = g_Q_h + ((size_t)b * N_ + nt * 128) * CI_;
    const bf16* Al = g_Q_l + ((size_t)b * N_ + nt * 128) * CI_;
    const bf16* Bh = g_K_h + ((size_t)b * M_ + mt * 128) * CI_;
    const bf16* Bl = g_K_l + ((size_t)b * M_ + mt * 128) * CI_;
    gemm_tile(smem, sb, Ah, Al, CI_, Bh, Bl, CI_, 4);

    const float* T = (const float*)smem;
    int tid = threadIdx.x;
    int n = tid & 127, h = tid >> 7;         // h in 0..3, 32 cols each
    float* row = g_S + ((size_t)b * N_ + nt * 128 + n) * M_ + mt * 128 + h * 32;
    const float* src = &T[n * TSTR + h * 32];
#pragma unroll
    for (int q = 0; q < 8; ++q)
        *(float4*)(row + 4 * q) = make_float4(src[4 * q], src[4 * q + 1],
                                              src[4 * q + 2], src[4 * q + 3]);
}

// Softmax rows of 1024 -> split-bf16 P
__global__ void __launch_bounds__(256) softmax_kernel() {
    const int warp = threadIdx.x >> 5, lane = threadIdx.x & 31;
    const size_t row = (size_t)blockIdx.x * 8 + warp;
    const float* S = g_S + row * M_;
    bf16* Ph = g_P_h + row * M_;
    bf16* Pl = g_P_l + row * M_;
    float v[32];
    float mx = -INFINITY;
#pragma unroll
    for (int i = 0; i < 32; ++i) { v[i] = S[lane + i * 32]; mx = fmaxf(mx, v[i]); }
#pragma unroll
    for (int o = 16; o > 0; o >>= 1) mx = fmaxf(mx, __shfl_xor_sync(0xffffffffu, mx, o));
    float s = 0.0f;
#pragma unroll
    for (int i = 0; i < 32; ++i) { v[i] = __expf(v[i] - mx); s += v[i]; }
#pragma unroll
    for (int o = 16; o > 0; o >>= 1) s += __shfl_xor_sync(0xffffffffu, s, o);
    const float inv = 1.0f / s;
#pragma unroll
    for (int i = 0; i < 32; ++i) {
        float p = v[i] * inv;
        bf16 h, l; split_bf16(p, h, l);
        Ph[lane + i * 32] = h; Pl[lane + i * 32] = l;
    }
}

// PV: T[n][ci] = P . Vt^T (K=1024)
__global__ void __launch_bounds__(NTHREADS) pv_mma() {
    extern __shared__ char smem[];
    uint32_t sb = smem_u32(smem);
    int nt = blockIdx.x, b = blockIdx.y;
    const bf16* Ah = g_P_h + ((size_t)b * N_ + nt * 128) * M_;
    const bf16* Al = g_P_l + ((size_t)b * N_ + nt * 128) * M_;
    const bf16* Bh = g_Vt_h + (size_t)b * CI_ * M_;
    const bf16* Bl = g_Vt_l + (size_t)b * CI_ * M_;
    gemm_tile(smem, sb, Ah, Al, M_, Bh, Bl, M_, 32);

    const float* T = (const float*)smem;
    int tid = threadIdx.x;
    int n = tid & 127, h = tid >> 7;
    size_t base = ((size_t)b * N_ + nt * 128 + n) * CI_;
    const float* src = &T[n * TSTR];
#pragma unroll
    for (int c8 = 0; c8 < 4; ++c8) {
        int ci0 = h * 32 + c8 * 8;
        __align__(16) bf16 hs[8], ls[8];
#pragma unroll
        for (int q = 0; q < 8; ++q)
            split_bf16(src[ci0 + q], hs[q], ls[q]);
        *(uint4*)&g_Y_h[base + ci0] = *(const uint4*)hs;
        *(uint4*)&g_Y_l[base + ci0] = *(const uint4*)ls;
    }
}

// Wy: T[o][n] = Ww . Y^T + b (K=128), plus BN partial sums
__global__ void __launch_bounds__(NTHREADS) wy_mma(const float* __restrict__ Wb) {
    extern __shared__ char smem[];
    uint32_t sb = smem_u32(smem);
    int ot = blockIdx.x, nt = blockIdx.y, b = blockIdx.z;
    const bf16* Ah = g_Ww_h + (size_t)ot * 128 * CI_;
    const bf16* Al = g_Ww_l + (size_t)ot * 128 * CI_;
    const bf16* Bh = g_Y_h + ((size_t)b * N_ + nt * 128) * CI_;
    const bf16* Bl = g_Y_l + ((size_t)b * N_ + nt * 128) * CI_;
    gemm_tile(smem, sb, Ah, Al, CI_, Bh, Bl, CI_, 4);

    const float* T = (const float*)smem;
    int tid = threadIdx.x;
    int o = tid & 127, h = tid >> 7;         // h in 0..3, 32 n each
    float bv = Wb[ot * 128 + o];
    float* row = g_Wy + ((size_t)(b * C_ + ot * 128 + o)) * N_ + nt * 128 + h * 32;
    const float* src = &T[o * TSTR + h * 32];
    float s = 0.0f, q = 0.0f;
#pragma unroll
    for (int qd = 0; qd < 8; ++qd) {
        float v0 = src[4 * qd]     + bv;
        float v1 = src[4 * qd + 1] + bv;
        float v2 = src[4 * qd + 2] + bv;
        float v3 = src[4 * qd + 3] + bv;
        *(float4*)(row + 4 * qd) = make_float4(v0, v1, v2, v3);
        s += v0 + v1 + v2 + v3;
        q += v0 * v0 + v1 * v1 + v2 * v2 + v3 * v3;
    }
    atomicAdd(&g_sum[ot * 128 + o], s);
    atomicAdd(&g_sumsq[ot * 128 + o], q);
}

// BN + gamma/beta + residual
__global__ void __launch_bounds__(256) bn_out_kernel(const float* __restrict__ x,
                                                     const float* __restrict__ gamma,
                                                     const float* __restrict__ beta,
                                                     float* __restrict__ out) {
    const size_t idx = (size_t)blockIdx.x * 256 + threadIdx.x;
    const int o = (int)((idx >> 12) & (C_ - 1));
    const float cnt_inv = 1.0f / (float)(B_ * N_);
    float mean = g_sum[o] * cnt_inv;
    float var  = g_sumsq[o] * cnt_inv - mean * mean;
    float inv  = rsqrtf(var + 1e-5f);
    out[idx] = (g_Wy[idx] - mean) * inv * gamma[o] + beta[o] + x[idx];
}

// ---------------------------------------------------------------------------
extern "C" void kernel_launch(void* const* d_in, const int* in_sizes, int n_in,
                              void* d_out, int out_size) {
    const float* x       = (const float*)d_in[0];
    const float* theta_w = (const float*)d_in[1];
    const float* theta_b = (const float*)d_in[2];
    const float* phi_w   = (const float*)d_in[3];
    const float* phi_b   = (const float*)d_in[4];
    const float* gw      = (const float*)d_in[5];
    const float* gb      = (const float*)d_in[6];
    const float* W_w     = (const float*)d_in[7];
    const float* W_b     = (const float*)d_in[8];
    const float* gamma   = (const float*)d_in[9];
    const float* beta    = (const float*)d_in[10];
    float* out = (float*)d_out;

    static bool attr_done = false;
    if (!attr_done) {
        cudaFuncSetAttribute(qkv_mma,    cudaFuncAttributeMaxDynamicSharedMemorySize, SMEM_BYTES);
        cudaFuncSetAttribute(scores_mma, cudaFuncAttributeMaxDynamicSharedMemorySize, SMEM_BYTES);
        cudaFuncSetAttribute(pv_mma,     cudaFuncAttributeMaxDynamicSharedMemorySize, SMEM_BYTES);
        cudaFuncSetAttribute(wy_mma,     cudaFuncAttributeMaxDynamicSharedMemorySize, SMEM_BYTES);
        attr_done = true;
    }

    cvt_weights<<<128, 256>>>(theta_w, phi_w, gw, W_w);
    xT_kernel<<<dim3(128, 8, 8), 256>>>(x);
    zero_stats_kernel<<<1, 256>>>();
    qkv_mma<<<dim3(32, 3, 8), NTHREADS, SMEM_BYTES>>>(theta_b, phi_b, gb);
    scores_mma<<<dim3(8, 32, 8), NTHREADS, SMEM_BYTES>>>();
    softmax_kernel<<<4096, 256>>>();
    pv_mma<<<dim3(32, 8), NTHREADS, SMEM_BYTES>>>();
    wy_mma<<<dim3(2, 32, 8), NTHREADS, SMEM_BYTES>>>(W_b);
    bn_out_kernel<<<32768, 256>>>(x, gamma, beta, out);
}

// round 7
// speedup vs baseline: 2.1526x; 1.2027x over previous
#include <cuda_runtime.h>
#include <cuda_bf16.h>
#include <mma.h>
#include <cstdint>
#include <math.h>

#define B_   8
#define C_   256
#define CI_  128
#define N_   4096
#define M_   1024

using bf16 = __nv_bfloat16;
namespace wm = nvcuda::wmma;

// ---------------------------------------------------------------------------
// Scratch (device globals; allocation-free)
// ---------------------------------------------------------------------------
__device__ __align__(16) bf16 g_xT_h[(size_t)B_*N_*C_];
__device__ __align__(16) bf16 g_xT_l[(size_t)B_*N_*C_];
__device__ __align__(16) bf16 g_w3_h[3*CI_*C_];
__device__ __align__(16) bf16 g_w3_l[3*CI_*C_];
__device__ __align__(16) bf16 g_Ww_h[C_*CI_];
__device__ __align__(16) bf16 g_Ww_l[C_*CI_];
__device__ __align__(16) bf16 g_Q_h[(size_t)B_*N_*CI_];
__device__ __align__(16) bf16 g_Q_l[(size_t)B_*N_*CI_];
__device__ __align__(16) bf16 g_K_h[(size_t)B_*M_*CI_];
__device__ __align__(16) bf16 g_K_l[(size_t)B_*M_*CI_];
__device__ __align__(16) bf16 g_Vt_h[(size_t)B_*CI_*M_];
__device__ __align__(16) bf16 g_Vt_l[(size_t)B_*CI_*M_];
__device__ __align__(16) float g_S  [(size_t)B_*N_*M_];
__device__ __align__(16) bf16 g_P_h[(size_t)B_*N_*M_];
__device__ __align__(16) bf16 g_P_l[(size_t)B_*N_*M_];
__device__ __align__(16) bf16 g_Y_h[(size_t)B_*N_*CI_];
__device__ __align__(16) bf16 g_Y_l[(size_t)B_*N_*CI_];
__device__ __align__(16) float g_Wy [(size_t)B_*C_*N_];
__device__ float g_sum[C_], g_sumsq[C_];

// ---------------------------------------------------------------------------
// Helpers
// ---------------------------------------------------------------------------
__device__ __forceinline__ uint32_t smem_u32(const void* p) {
    uint32_t a;
    asm("{ .reg .u64 t; cvta.to.shared.u64 t, %1; cvt.u32.u64 %0, t; }" : "=r"(a) : "l"(p));
    return a;
}
#define CP16(d, s)  asm volatile("cp.async.cg.shared.global [%0], [%1], 16;" :: "r"(d), "l"(s))
#define CPCOMMIT()  asm volatile("cp.async.commit_group;" ::: "memory")
#define CPWAIT0()   asm volatile("cp.async.wait_group 0;" ::: "memory")

__device__ __forceinline__ void split_bf16(float v, bf16& h, bf16& l) {
    h = __float2bfloat16(v);
    l = __float2bfloat16(v - __bfloat162float(h));
}

// ---------------------------------------------------------------------------
// Shared 128x128 GEMM core (split-bf16, 3 MMA products, cp.async 2-stage)
// 256 threads, 8 warps, warp tile 64x32 (4x2 fragments), 2 CTAs/SM.
// Result left in shared fp32 tile T (row stride TSTR).
// ---------------------------------------------------------------------------
#define TSTR 132
#define TILE_BYTES  10240          // 128 rows x 40 bf16 (pad) x 2B
#define STAGE_BYTES (4*TILE_BYTES) // Ah, Al, Bh, Bl
#define SMEM_BYTES  (2*STAGE_BYTES)  // 81920; fp32 T (128*132*4=67584) reuses it
#define NTHREADS 256

__device__ __forceinline__ void gemm_tile(char* smem, uint32_t sb,
        const bf16* __restrict__ Ah, const bf16* __restrict__ Al, int strA,
        const bf16* __restrict__ Bh, const bf16* __restrict__ Bl, int strB,
        int kchunks) {
    const int tid = threadIdx.x;
    const int wid = tid >> 5;
    const int wmi = wid >> 2;      // 0..1 : 64 rows each
    const int wni = wid & 3;       // 0..3 : 32 cols each

    wm::fragment<wm::accumulator, 16, 16, 16, float> acc[4][2];
#pragma unroll
    for (int fm = 0; fm < 4; ++fm)
#pragma unroll
        for (int fn = 0; fn < 2; ++fn)
            wm::fill_fragment(acc[fm][fn], 0.0f);

    auto issue = [&](int kc, int s) {
        const bf16* srcs[4] = { Ah + kc * 32, Al + kc * 32, Bh + kc * 32, Bl + kc * 32 };
#pragma unroll
        for (int t = 0; t < 4; ++t) {
            const int str = (t < 2) ? strA : strB;
            const bf16* base = srcs[t];
            const uint32_t dbase = sb + s * STAGE_BYTES + t * TILE_BYTES;
#pragma unroll
            for (int i = 0; i < 2; ++i) {
                int idx = i * 256 + tid;       // 512 chunks of 16B
                int r = idx >> 2, c = idx & 3;
                CP16(dbase + r * 80 + c * 16, base + (size_t)r * str + c * 8);
            }
        }
        CPCOMMIT();
    };

    issue(0, 0);
    for (int kc = 0; kc < kchunks; ++kc) {
        CPWAIT0();
        __syncthreads();
        if (kc + 1 < kchunks) issue(kc + 1, (kc + 1) & 1);
        const bf16* sAh = (const bf16*)(smem + (kc & 1) * STAGE_BYTES);
        const bf16* sAl = sAh + 5120;
        const bf16* sBh = sAh + 10240;
        const bf16* sBl = sAh + 15360;
#pragma unroll
        for (int kk = 0; kk < 32; kk += 16) {
            // Load B fragments first (kept live), then stream A fragments
            // one row-band at a time to cap register pressure (<128 regs).
            wm::fragment<wm::matrix_b, 16, 16, 16, bf16, wm::col_major> bh[2], bl[2];
#pragma unroll
            for (int f = 0; f < 2; ++f) {
                wm::load_matrix_sync(bh[f], sBh + (wni * 32 + f * 16) * 40 + kk, 40);
                wm::load_matrix_sync(bl[f], sBl + (wni * 32 + f * 16) * 40 + kk, 40);
            }
#pragma unroll
            for (int fm = 0; fm < 4; ++fm) {
                wm::fragment<wm::matrix_a, 16, 16, 16, bf16, wm::row_major> ah, al;
                wm::load_matrix_sync(ah, sAh + (wmi * 64 + fm * 16) * 40 + kk, 40);
                wm::load_matrix_sync(al, sAl + (wmi * 64 + fm * 16) * 40 + kk, 40);
#pragma unroll
                for (int fn = 0; fn < 2; ++fn) {
                    wm::mma_sync(acc[fm][fn], ah, bh[fn], acc[fm][fn]);
                    wm::mma_sync(acc[fm][fn], ah, bl[fn], acc[fm][fn]);
                    wm::mma_sync(acc[fm][fn], al, bh[fn], acc[fm][fn]);
                }
            }
        }
    }
    __syncthreads();                       // all warps done reading stages
    float* T = (float*)smem;
#pragma unroll
    for (int fm = 0; fm < 4; ++fm)
#pragma unroll
        for (int fn = 0; fn < 2; ++fn)
            wm::store_matrix_sync(T + (wmi * 64 + fm * 16) * TSTR + wni * 32 + fn * 16,
                                  acc[fm][fn], TSTR, wm::mem_row_major);
    __syncthreads();
}

// ---------------------------------------------------------------------------
// Prep kernels
// ---------------------------------------------------------------------------
__global__ void __launch_bounds__(256) cvt_weights(
    const float* __restrict__ tw, const float* __restrict__ pw,
    const float* __restrict__ gw, const float* __restrict__ ww) {
    int i = blockIdx.x * 256 + threadIdx.x;      // 32768 threads
    bf16 h, l;
    split_bf16(tw[i], h, l); g_w3_h[i] = h;           g_w3_l[i] = l;
    split_bf16(pw[i], h, l); g_w3_h[32768 + i] = h;   g_w3_l[32768 + i] = l;
    split_bf16(gw[i], h, l); g_w3_h[65536 + i] = h;   g_w3_l[65536 + i] = l;
    split_bf16(ww[i], h, l); g_Ww_h[i] = h;           g_Ww_l[i] = l;
}

__global__ void __launch_bounds__(256) xT_kernel(const float* __restrict__ x) {
    __shared__ float t[32][33];
    int n0 = blockIdx.x * 32, c0 = blockIdx.y * 32, b = blockIdx.z;
    int j = threadIdx.x & 31, r = threadIdx.x >> 5;
    const float* xb = x + ((size_t)b * C_ + c0) * N_ + n0;
#pragma unroll
    for (int rr = 0; rr < 32; rr += 8)
        t[r + rr][j] = xb[(size_t)(r + rr) * N_ + j];
    __syncthreads();
#pragma unroll
    for (int rr = 0; rr < 32; rr += 8) {
        float v = t[j][r + rr];
        bf16 h, l; split_bf16(v, h, l);
        size_t o = ((size_t)b * N_ + n0 + r + rr) * C_ + c0 + j;
        g_xT_h[o] = h; g_xT_l[o] = l;
    }
}

__global__ void zero_stats_kernel() {
    int t = threadIdx.x;
    if (t < C_) { g_sum[t] = 0.0f; g_sumsq[t] = 0.0f; }
}

// ---------------------------------------------------------------------------
// GEMM kernels (256 threads, 2 CTAs/SM)
// ---------------------------------------------------------------------------
// QKV conv: T[ci][n] = w . xT^T (K=256). conv1/2 add in-tile 2x2 maxpool.
__global__ void __launch_bounds__(NTHREADS, 2) qkv_mma(
    const float* __restrict__ tb, const float* __restrict__ pb,
    const float* __restrict__ gbias) {
    extern __shared__ char smem[];
    uint32_t sb = smem_u32(smem);
    int nt = blockIdx.x, conv = blockIdx.y, b = blockIdx.z;
    const bf16* Ah = g_w3_h + conv * (CI_ * C_);
    const bf16* Al = g_w3_l + conv * (CI_ * C_);
    const bf16* Bh = g_xT_h + ((size_t)b * N_ + nt * 128) * C_;
    const bf16* Bl = g_xT_l + ((size_t)b * N_ + nt * 128) * C_;
    gemm_tile(smem, sb, Ah, Al, C_, Bh, Bl, C_, 8);

    const float* T = (const float*)smem;
    const float* bias = (conv == 0) ? tb : (conv == 1) ? pb : gbias;
    int tid = threadIdx.x;

    if (conv == 0) {
        // transpose: thread owns column n, writes contiguous ci runs
        int n = tid & 127, h = tid >> 7;
        size_t base = ((size_t)b * N_ + nt * 128 + n) * CI_;
#pragma unroll
        for (int c8 = 0; c8 < 8; ++c8) {
            int ci0 = h * 64 + c8 * 8;
            __align__(16) bf16 hs[8], ls[8];
#pragma unroll
            for (int q = 0; q < 8; ++q) {
                float v = T[(ci0 + q) * TSTR + n] + bias[ci0 + q];
                split_bf16(v, hs[q], ls[q]);
            }
            *(uint4*)&g_Q_h[base + ci0] = *(const uint4*)hs;
            *(uint4*)&g_Q_l[base + ci0] = *(const uint4*)ls;
        }
    } else if (conv == 1) {
        // maxpool -> K[m][ci]: thread owns m-col c, writes 16 contiguous ci
        int c = tid & 31, h = tid >> 5;          // h in 0..7
        int m = nt * 32 + c;
        size_t base = ((size_t)b * M_ + m) * CI_ + h * 16;
        __align__(16) bf16 hs[16], ls[16];
#pragma unroll
        for (int q = 0; q < 16; ++q) {
            int ci = h * 16 + q;
            const float* row = &T[ci * TSTR];
            float v = fmaxf(fmaxf(row[2 * c], row[2 * c + 1]),
                            fmaxf(row[64 + 2 * c], row[65 + 2 * c])) + bias[ci];
            split_bf16(v, hs[q], ls[q]);
        }
        *(uint4*)&g_K_h[base]     = *(const uint4*)hs;
        *(uint4*)&g_K_h[base + 8] = *(const uint4*)(hs + 8);
        *(uint4*)&g_K_l[base]     = *(const uint4*)ls;
        *(uint4*)&g_K_l[base + 8] = *(const uint4*)(ls + 8);
    } else {
        // maxpool -> Vt[ci][m]: thread owns ci row, writes 16 contiguous m
        int ci = tid & 127, h = tid >> 7;        // h in 0..1
        const float* row = &T[ci * TSTR];
        float bv = bias[ci];
        size_t base = ((size_t)b * CI_ + ci) * M_ + nt * 32 + h * 16;
        __align__(16) bf16 hs[16], ls[16];
#pragma unroll
        for (int q = 0; q < 16; ++q) {
            int c = h * 16 + q;
            float v = fmaxf(fmaxf(row[2 * c], row[2 * c + 1]),
                            fmaxf(row[64 + 2 * c], row[65 + 2 * c])) + bv;
            split_bf16(v, hs[q], ls[q]);
        }
        *(uint4*)&g_Vt_h[base]     = *(const uint4*)hs;
        *(uint4*)&g_Vt_h[base + 8] = *(const uint4*)(hs + 8);
        *(uint4*)&g_Vt_l[base]     = *(const uint4*)ls;
        *(uint4*)&g_Vt_l[base + 8] = *(const uint4*)(ls + 8);
    }
}

// Scores: T[n][m] = Q . K^T (K=128)
__global__ void __launch_bounds__(NTHREADS, 2) scores_mma() {
    extern __shared__ char smem[];
    uint32_t sb = smem_u32(smem);
    int mt = blockIdx.x, nt = blockIdx.y, b = blockIdx.z;
    const bf16* Ah = g_Q_h + ((size_t)b * N_ + nt * 128) * CI_;
    const bf16* Al = g_Q_l + ((size_t)b * N_ + nt * 128) * CI_;
    const bf16* Bh = g_K_h + ((size_t)b * M_ + mt * 128) * CI_;
    const bf16* Bl = g_K_l + ((size_t)b * M_ + mt * 128) * CI_;
    gemm_tile(smem, sb, Ah, Al, CI_, Bh, Bl, CI_, 4);

    const float* T = (const float*)smem;
    int tid = threadIdx.x;
    int n = tid & 127, h = tid >> 7;
    float* row = g_S + ((size_t)b * N_ + nt * 128 + n) * M_ + mt * 128 + h * 64;
    const float* src = &T[n * TSTR + h * 64];
#pragma unroll
    for (int q = 0; q < 16; ++q)
        *(float4*)(row + 4 * q) = make_float4(src[4 * q], src[4 * q + 1],
                                              src[4 * q + 2], src[4 * q + 3]);
}

// Softmax rows of 1024 -> split-bf16 P
__global__ void __launch_bounds__(256) softmax_kernel() {
    const int warp = threadIdx.x >> 5, lane = threadIdx.x & 31;
    const size_t row = (size_t)blockIdx.x * 8 + warp;
    const float* S = g_S + row * M_;
    bf16* Ph = g_P_h + row * M_;
    bf16* Pl = g_P_l + row * M_;
    float v[32];
    float mx = -INFINITY;
#pragma unroll
    for (int i = 0; i < 32; ++i) { v[i] = S[lane + i * 32]; mx = fmaxf(mx, v[i]); }
#pragma unroll
    for (int o = 16; o > 0; o >>= 1) mx = fmaxf(mx, __shfl_xor_sync(0xffffffffu, mx, o));
    float s = 0.0f;
#pragma unroll
    for (int i = 0; i < 32; ++i) { v[i] = __expf(v[i] - mx); s += v[i]; }
#pragma unroll
    for (int o = 16; o > 0; o >>= 1) s += __shfl_xor_sync(0xffffffffu, s, o);
    const float inv = 1.0f / s;
#pragma unroll
    for (int i = 0; i < 32; ++i) {
        float p = v[i] * inv;
        bf16 h, l; split_bf16(p, h, l);
        Ph[lane + i * 32] = h; Pl[lane + i * 32] = l;
    }
}

// PV: T[n][ci] = P . Vt^T (K=1024)
__global__ void __launch_bounds__(NTHREADS, 2) pv_mma() {
    extern __shared__ char smem[];
    uint32_t sb = smem_u32(smem);
    int nt = blockIdx.x, b = blockIdx.y;
    const bf16* Ah = g_P_h + ((size_t)b * N_ + nt * 128) * M_;
    const bf16* Al = g_P_l + ((size_t)b * N_ + nt * 128) * M_;
    const bf16* Bh = g_Vt_h + (size_t)b * CI_ * M_;
    const bf16* Bl = g_Vt_l + (size_t)b * CI_ * M_;
    gemm_tile(smem, sb, Ah, Al, M_, Bh, Bl, M_, 32);

    const float* T = (const float*)smem;
    int tid = threadIdx.x;
    int n = tid & 127, h = tid >> 7;
    size_t base = ((size_t)b * N_ + nt * 128 + n) * CI_;
    const float* src = &T[n * TSTR];
#pragma unroll
    for (int c8 = 0; c8 < 8; ++c8) {
        int ci0 = h * 64 + c8 * 8;
        __align__(16) bf16 hs[8], ls[8];
#pragma unroll
        for (int q = 0; q < 8; ++q)
            split_bf16(src[ci0 + q], hs[q], ls[q]);
        *(uint4*)&g_Y_h[base + ci0] = *(const uint4*)hs;
        *(uint4*)&g_Y_l[base + ci0] = *(const uint4*)ls;
    }
}

// Wy: T[o][n] = Ww . Y^T + b (K=128), plus BN partial sums
__global__ void __launch_bounds__(NTHREADS, 2) wy_mma(const float* __restrict__ Wb) {
    extern __shared__ char smem[];
    uint32_t sb = smem_u32(smem);
    int ot = blockIdx.x, nt = blockIdx.y, b = blockIdx.z;
    const bf16* Ah = g_Ww_h + (size_t)ot * 128 * CI_;
    const bf16* Al = g_Ww_l + (size_t)ot * 128 * CI_;
    const bf16* Bh = g_Y_h + ((size_t)b * N_ + nt * 128) * CI_;
    const bf16* Bl = g_Y_l + ((size_t)b * N_ + nt * 128) * CI_;
    gemm_tile(smem, sb, Ah, Al, CI_, Bh, Bl, CI_, 4);

    const float* T = (const float*)smem;
    int tid = threadIdx.x;
    int o = tid & 127, h = tid >> 7;
    float bv = Wb[ot * 128 + o];
    float* row = g_Wy + ((size_t)(b * C_ + ot * 128 + o)) * N_ + nt * 128 + h * 64;
    const float* src = &T[o * TSTR + h * 64];
    float s = 0.0f, q = 0.0f;
#pragma unroll
    for (int qd = 0; qd < 16; ++qd) {
        float v0 = src[4 * qd]     + bv;
        float v1 = src[4 * qd + 1] + bv;
        float v2 = src[4 * qd + 2] + bv;
        float v3 = src[4 * qd + 3] + bv;
        *(float4*)(row + 4 * qd) = make_float4(v0, v1, v2, v3);
        s += v0 + v1 + v2 + v3;
        q += v0 * v0 + v1 * v1 + v2 * v2 + v3 * v3;
    }
    atomicAdd(&g_sum[ot * 128 + o], s);
    atomicAdd(&g_sumsq[ot * 128 + o], q);
}

// BN + gamma/beta + residual
__global__ void __launch_bounds__(256) bn_out_kernel(const float* __restrict__ x,
                                                     const float* __restrict__ gamma,
                                                     const float* __restrict__ beta,
                                                     float* __restrict__ out) {
    const size_t idx = (size_t)blockIdx.x * 256 + threadIdx.x;
    const int o = (int)((idx >> 12) & (C_ - 1));
    const float cnt_inv = 1.0f / (float)(B_ * N_);
    float mean = g_sum[o] * cnt_inv;
    float var  = g_sumsq[o] * cnt_inv - mean * mean;
    float inv  = rsqrtf(var + 1e-5f);
    out[idx] = (g_Wy[idx] - mean) * inv * gamma[o] + beta[o] + x[idx];
}

// ---------------------------------------------------------------------------
extern "C" void kernel_launch(void* const* d_in, const int* in_sizes, int n_in,
                              void* d_out, int out_size) {
    const float* x       = (const float*)d_in[0];
    const float* theta_w = (const float*)d_in[1];
    const float* theta_b = (const float*)d_in[2];
    const float* phi_w   = (const float*)d_in[3];
    const float* phi_b   = (const float*)d_in[4];
    const float* gw      = (const float*)d_in[5];
    const float* gb      = (const float*)d_in[6];
    const float* W_w     = (const float*)d_in[7];
    const float* W_b     = (const float*)d_in[8];
    const float* gamma   = (const float*)d_in[9];
    const float* beta    = (const float*)d_in[10];
    float* out = (float*)d_out;

    static bool attr_done = false;
    if (!attr_done) {
        cudaFuncSetAttribute(qkv_mma,    cudaFuncAttributeMaxDynamicSharedMemorySize, SMEM_BYTES);
        cudaFuncSetAttribute(scores_mma, cudaFuncAttributeMaxDynamicSharedMemorySize, SMEM_BYTES);
        cudaFuncSetAttribute(pv_mma,     cudaFuncAttributeMaxDynamicSharedMemorySize, SMEM_BYTES);
        cudaFuncSetAttribute(wy_mma,     cudaFuncAttributeMaxDynamicSharedMemorySize, SMEM_BYTES);
        attr_done = true;
    }

    cvt_weights<<<128, 256>>>(theta_w, phi_w, gw, W_w);
    xT_kernel<<<dim3(128, 8, 8), 256>>>(x);
    zero_stats_kernel<<<1, 256>>>();
    qkv_mma<<<dim3(32, 3, 8), NTHREADS, SMEM_BYTES>>>(theta_b, phi_b, gb);
    scores_mma<<<dim3(8, 32, 8), NTHREADS, SMEM_BYTES>>>();
    softmax_kernel<<<4096, 256>>>();
    pv_mma<<<dim3(32, 8), NTHREADS, SMEM_BYTES>>>();
    wy_mma<<<dim3(2, 32, 8), NTHREADS, SMEM_BYTES>>>(W_b);
    bn_out_kernel<<<32768, 256>>>(x, gamma, beta, out);
}